// round 1
// baseline (speedup 1.0000x reference)
#include <cuda_runtime.h>
#include <cstdint>
#include <climits>

// Problem dims (fixed for this dataset)
#define T_DIM   1000
#define B_DIM   32
#define N_DIM   2048
#define BN      (B_DIM * N_DIM)        // 65536
#define NCHUNK  10
#define CHUNK   (T_DIM / NCHUNK)       // 100
#define THREADS 256
#define NPT     4                       // neurons per thread (float4)
#define NEUR_PER_BLOCK (THREADS * NPT)  // 1024
#define BLOCKS_PER_B   (N_DIM / NEUR_PER_BLOCK) // 2

// Output layout (concatenated, tuple order):
// firing_rates[BN] | cv_isi[BN] | synchrony[B] | total_spikes[BN] | active[B]
#define OFF_RATE 0
#define OFF_CV   (BN)
#define OFF_SYNC (2 * BN)
#define OFF_TOT  (2 * BN + B_DIM)
#define OFF_ACT  (3 * BN + B_DIM)

// Scratch (device globals; no allocation allowed)
__device__ int g_tot  [NCHUNK * BN];
__device__ int g_first[NCHUNK * BN];
__device__ int g_last [NCHUNK * BN];
__device__ int g_sg2  [NCHUNK * BN];   // sum of squared gaps within chunk (corrected)
__device__ int g_pop  [B_DIM * T_DIM]; // population activity, [b][t]

// ---------------------------------------------------------------------------
// Kernel 0: zero the accumulators that are built via atomics each launch
// ---------------------------------------------------------------------------
__global__ void k_zero(float* __restrict__ out) {
    int i = blockIdx.x * blockDim.x + threadIdx.x;
    if (i < B_DIM * T_DIM) g_pop[i] = 0;
    if (i < B_DIM) out[OFF_ACT + i] = 0.0f;
}

// ---------------------------------------------------------------------------
// Kernel 1: single streaming pass. Each thread owns 4 consecutive neurons of
// one batch, scans CHUNK time steps. ISI state per neuron: tot/first/last/sg2.
// Spurious first-gap (measured from last=-1) is subtracted in the epilogue.
// Per-t population count is REDUX'd per warp, staged in smem, then one
// global int atomicAdd per (block, t).
// ---------------------------------------------------------------------------
__global__ __launch_bounds__(THREADS) void k_main(const float* __restrict__ sp) {
    const int c    = blockIdx.y;                 // time chunk
    const int gb   = blockIdx.x;                 // 0..B*BLOCKS_PER_B-1
    const int b    = gb / BLOCKS_PER_B;
    const int nblk = gb % BLOCKS_PER_B;
    const int tid  = threadIdx.x;
    const int wid  = tid >> 5;
    const int lane = tid & 31;
    const int n0   = nblk * NEUR_PER_BLOCK + tid * NPT;
    const int t0   = c * CHUNK;

    const float4* __restrict__ p =
        (const float4*)(sp + (size_t)t0 * BN + (size_t)b * N_DIM + n0);
    const size_t stride4 = BN / 4;

    int last0 = -1, last1 = -1, last2 = -1, last3 = -1;
    int fst0 = INT_MAX, fst1 = INT_MAX, fst2 = INT_MAX, fst3 = INT_MAX;
    int tot0 = 0, tot1 = 0, tot2 = 0, tot3 = 0;
    int sg0 = 0, sg1 = 0, sg2 = 0, sg3 = 0;

    __shared__ int s_pop[THREADS / 32][CHUNK];

    #pragma unroll 4
    for (int tl = 0; tl < CHUNK; ++tl) {
        float4 x = p[(size_t)tl * stride4];
        int t = t0 + tl;
        int cc = 0;
        if (x.x != 0.0f) { int g = t - last0; sg0 += g * g; fst0 = min(fst0, t); last0 = t; tot0++; cc++; }
        if (x.y != 0.0f) { int g = t - last1; sg1 += g * g; fst1 = min(fst1, t); last1 = t; tot1++; cc++; }
        if (x.z != 0.0f) { int g = t - last2; sg2 += g * g; fst2 = min(fst2, t); last2 = t; tot2++; cc++; }
        if (x.w != 0.0f) { int g = t - last3; sg3 += g * g; fst3 = min(fst3, t); last3 = t; tot3++; cc++; }
        unsigned wsum = __reduce_add_sync(0xffffffffu, (unsigned)cc);
        if (lane == 0) s_pop[wid][tl] = (int)wsum;
    }

    // remove spurious first-gap (computed against last = -1)
    if (tot0 > 0) sg0 -= (fst0 + 1) * (fst0 + 1);
    if (tot1 > 0) sg1 -= (fst1 + 1) * (fst1 + 1);
    if (tot2 > 0) sg2 -= (fst2 + 1) * (fst2 + 1);
    if (tot3 > 0) sg3 -= (fst3 + 1) * (fst3 + 1);

    const int idx = c * BN + b * N_DIM + n0;     // n0 multiple of 4 -> aligned
    *(int4*)&g_tot  [idx] = make_int4(tot0, tot1, tot2, tot3);
    *(int4*)&g_first[idx] = make_int4(fst0, fst1, fst2, fst3);
    *(int4*)&g_last [idx] = make_int4(last0, last1, last2, last3);
    *(int4*)&g_sg2  [idx] = make_int4(sg0, sg1, sg2, sg3);

    __syncthreads();
    for (int tl = tid; tl < CHUNK; tl += THREADS) {
        int ssum = 0;
        #pragma unroll
        for (int w = 0; w < THREADS / 32; ++w) ssum += s_pop[w][tl];
        atomicAdd(&g_pop[b * T_DIM + t0 + tl], ssum);
    }
}

// ---------------------------------------------------------------------------
// Kernel 2: combine the NCHUNK segment partials per neuron (ordered), emit
// firing_rates, cv_isi, total_spikes, and warp-aggregated active_neurons.
// ---------------------------------------------------------------------------
__global__ __launch_bounds__(256) void k_final(float* __restrict__ out) {
    const int i = blockIdx.x * blockDim.x + threadIdx.x;   // 0..BN-1
    const int b = i >> 11;                                  // i / N_DIM

    int tot = 0, fst = 0, lst = 0, sg2 = 0;
    bool any = false;
    #pragma unroll
    for (int c = 0; c < NCHUNK; ++c) {
        int t = g_tot[c * BN + i];
        if (t == 0) continue;
        int f  = g_first[c * BN + i];
        int l  = g_last [c * BN + i];
        int s2 = g_sg2  [c * BN + i];
        if (!any) { any = true; tot = t; fst = f; lst = l; sg2 = s2; }
        else {
            int g = f - lst;
            sg2 += g * g + s2;
            lst = l;
            tot += t;
        }
    }

    float ftot = (float)tot;
    float rate = ftot * (1.0f / ((float)T_DIM * 0.001f));
    float cv = 0.0f;
    int cnt = tot - 1;
    if (cnt >= 1) {
        float fcnt  = (float)cnt;
        float sum_g = (float)(lst - fst);
        float mean  = sum_g / fcnt;
        float var   = ((float)sg2 - fcnt * mean * mean) / fmaxf(fcnt - 1.0f, 1.0f);
        cv = sqrtf(fmaxf(var, 0.0f)) / fmaxf(mean, 1e-12f);
    }

    out[OFF_RATE + i] = rate;
    out[OFF_CV   + i] = cv;
    out[OFF_TOT  + i] = ftot;

    unsigned act = __reduce_add_sync(0xffffffffu, (unsigned)(tot > 0));
    if ((threadIdx.x & 31) == 0)
        atomicAdd(&out[OFF_ACT + b], (float)act);   // integer-valued -> exact/deterministic
}

// ---------------------------------------------------------------------------
// Kernel 3: lag-1 circular autocorrelation of pop[b][t]. One block per batch.
// In exact arithmetic Sy == Sx (same multiset), so den = Sx.
// ---------------------------------------------------------------------------
__global__ __launch_bounds__(256) void k_sync(float* __restrict__ out) {
    const int b   = blockIdx.x;
    const int tid = threadIdx.x;
    __shared__ float  sp[T_DIM];
    __shared__ double red[2][8];

    for (int t = tid; t < T_DIM; t += blockDim.x)
        sp[t] = (float)g_pop[b * T_DIM + t];
    __syncthreads();

    // mean (exact: integer sums)
    double s = 0.0;
    for (int t = tid; t < T_DIM; t += blockDim.x) s += (double)sp[t];
    for (int o = 16; o > 0; o >>= 1) s += __shfl_down_sync(0xffffffffu, s, o);
    if ((tid & 31) == 0) red[0][tid >> 5] = s;
    __syncthreads();
    double total = 0.0;
    #pragma unroll
    for (int w = 0; w < 8; ++w) total += red[0][w];
    const double mean = total / (double)T_DIM;
    __syncthreads();

    double num = 0.0, sx = 0.0;
    for (int t = tid; t < T_DIM; t += blockDim.x) {
        double xm = (double)sp[t] - mean;
        double ym = (double)sp[(t == 0) ? (T_DIM - 1) : (t - 1)] - mean;
        num += xm * ym;
        sx  += xm * xm;
    }
    for (int o = 16; o > 0; o >>= 1) {
        num += __shfl_down_sync(0xffffffffu, num, o);
        sx  += __shfl_down_sync(0xffffffffu, sx,  o);
    }
    if ((tid & 31) == 0) { red[0][tid >> 5] = num; red[1][tid >> 5] = sx; }
    __syncthreads();
    if (tid == 0) {
        double n2 = 0.0, x2 = 0.0;
        #pragma unroll
        for (int w = 0; w < 8; ++w) { n2 += red[0][w]; x2 += red[1][w]; }
        float r = 0.0f;
        if (x2 > 0.0) r = (float)(n2 / (x2 > 1e-12 ? x2 : 1e-12));
        out[OFF_SYNC + b] = r;
    }
}

// ---------------------------------------------------------------------------
extern "C" void kernel_launch(void* const* d_in, const int* in_sizes, int n_in,
                              void* d_out, int out_size) {
    const float* sp = (const float*)d_in[0];
    float* out = (float*)d_out;

    int zn = B_DIM * T_DIM;                    // covers OFF_ACT zeroing too
    k_zero<<<(zn + 255) / 256, 256>>>(out);

    dim3 g1(B_DIM * BLOCKS_PER_B, NCHUNK);     // 64 x 10 blocks
    k_main<<<g1, THREADS>>>(sp);

    k_final<<<BN / 256, 256>>>(out);
    k_sync<<<B_DIM, 256>>>(out);
}